// round 4
// baseline (speedup 1.0000x reference)
#include <cuda_runtime.h>
#include <cstdint>

// N_NODES=50000, N_EDGES=800000, IN=128, HID=128, OUT=64. int32 edge indices.
#define NMAX 50048
#define EMAX 800000
#define IN_DIM 128
#define HID_DIM 128
#define OUT_DIM 64

__device__ int   g_degi[NMAX];            // int in-degree (at dst)
__device__ int   g_rowptr[NMAX + 1];      // CSR row pointers (by dst)
__device__ int   g_cursor[NMAX];          // fill cursors
__device__ int   g_csr_src[EMAX];         // src ids grouped by dst
__device__ float g_dinv[NMAX];            // rsqrt(deg) or 0
__device__ float g_h1[NMAX * HID_DIM];    // dinv[row] * (x @ W1)
__device__ float g_acc1[NMAX * HID_DIM];  // agg1 output (includes *dinv[dst] + b1)
__device__ float g_h2[NMAX * OUT_DIM];    // dinv[row] * (relu(acc1) @ W2)

// ---------------------------------------------------------------------------
__global__ void deg_kernel(const int* __restrict__ dst, int* __restrict__ degi, int E) {
    int i = blockIdx.x * blockDim.x + threadIdx.x;
    if (i < E) atomicAdd(&degi[dst[i]], 1);
}

// Single-block exclusive scan over degi -> rowptr/cursor, plus dinv.
__global__ void scan_kernel(const int* __restrict__ degi, int* __restrict__ rowptr,
                            int* __restrict__ cursor, float* __restrict__ dinv,
                            int N, int E) {
    __shared__ int warp_sums[32];
    int t = threadIdx.x;                    // 1024 threads
    int CH = (N + 1023) >> 10;
    int lo = t * CH, hi = min(lo + CH, N);
    int sum = 0;
    for (int i = lo; i < hi; i++) sum += degi[i];

    int lane = t & 31, wid = t >> 5;
    int v = sum;
#pragma unroll
    for (int o = 1; o < 32; o <<= 1) {
        int u = __shfl_up_sync(~0u, v, o);
        if (lane >= o) v += u;
    }
    if (lane == 31) warp_sums[wid] = v;
    __syncthreads();
    if (wid == 0) {
        int w = warp_sums[lane];
#pragma unroll
        for (int o = 1; o < 32; o <<= 1) {
            int u = __shfl_up_sync(~0u, w, o);
            if (lane >= o) w += u;
        }
        warp_sums[lane] = w;
    }
    __syncthreads();
    int run = v - sum + (wid > 0 ? warp_sums[wid - 1] : 0);  // exclusive prefix
    for (int i = lo; i < hi; i++) {
        int d = degi[i];
        rowptr[i] = run;
        cursor[i] = run;
        dinv[i] = d > 0 ? rsqrtf((float)d) : 0.0f;
        run += d;
    }
    if (t == 0) rowptr[N] = E;
}

// Bucket fill: csr_src grouped by dst.
__global__ void fill_kernel(const int* __restrict__ src, const int* __restrict__ dst,
                            int* __restrict__ cursor, int* __restrict__ csr_src, int E) {
    int e = blockIdx.x * blockDim.x + threadIdx.x;
    if (e < E) {
        int pos = atomicAdd(&cursor[dst[e]], 1);
        csr_src[pos] = src[e];
    }
}

// ---------------------------------------------------------------------------
// Tiled fp32 GEMM: Y[M,N] = act(X)[M,K] @ W[K,N], then Y[row] *= scale[row].
// 256 threads, 64-row tile, W resident in smem, conflict-free vector LDS.
template <int K, int N, bool RELU>
__global__ void gemm_kernel(const float* __restrict__ X, const float* __restrict__ W,
                            const float* __restrict__ scale,
                            float* __restrict__ Y, int M) {
    constexpr int ROWS = 64;
    constexpr int CPT = N / 32;
    extern __shared__ float smem[];
    float* Ws = smem;              // K*N
    float* Xs = smem + K * N;      // ROWS*K

    int t = threadIdx.x;
    for (int i = t; i < K * N / 4; i += 256)
        ((float4*)Ws)[i] = ((const float4*)W)[i];

    int row0 = blockIdx.x * ROWS;
    constexpr int K4 = K / 4;
    for (int i = t; i < ROWS * K4; i += 256) {
        int gr = row0 + i / K4;
        float4 v = make_float4(0.f, 0.f, 0.f, 0.f);
        if (gr < M) v = ((const float4*)X)[(size_t)gr * K4 + (i % K4)];
        if (RELU) {
            v.x = fmaxf(v.x, 0.f); v.y = fmaxf(v.y, 0.f);
            v.z = fmaxf(v.z, 0.f); v.w = fmaxf(v.w, 0.f);
        }
        ((float4*)Xs)[i] = v;
    }
    __syncthreads();

    int tx = t & 31;
    int ty = t >> 5;

    if constexpr (CPT == 4) {
        float4 acc[8];
#pragma unroll
        for (int r = 0; r < 8; r++) acc[r] = make_float4(0.f, 0.f, 0.f, 0.f);
#pragma unroll 4
        for (int k = 0; k < K; k += 4) {
            float4 bv[4];
#pragma unroll
            for (int j = 0; j < 4; j++)
                bv[j] = *(const float4*)&Ws[(k + j) * N + tx * 4];
#pragma unroll
            for (int r = 0; r < 8; r++) {
                float4 av = *(const float4*)&Xs[(ty * 8 + r) * K + k];
                acc[r].x += av.x * bv[0].x + av.y * bv[1].x + av.z * bv[2].x + av.w * bv[3].x;
                acc[r].y += av.x * bv[0].y + av.y * bv[1].y + av.z * bv[2].y + av.w * bv[3].y;
                acc[r].z += av.x * bv[0].z + av.y * bv[1].z + av.z * bv[2].z + av.w * bv[3].z;
                acc[r].w += av.x * bv[0].w + av.y * bv[1].w + av.z * bv[2].w + av.w * bv[3].w;
            }
        }
#pragma unroll
        for (int r = 0; r < 8; r++) {
            int gr = row0 + ty * 8 + r;
            if (gr < M) {
                float s = scale[gr];
                float4 o = acc[r];
                o.x *= s; o.y *= s; o.z *= s; o.w *= s;
                *(float4*)&Y[(size_t)gr * N + tx * 4] = o;
            }
        }
    } else {
        float2 acc[8];
#pragma unroll
        for (int r = 0; r < 8; r++) acc[r] = make_float2(0.f, 0.f);
#pragma unroll 4
        for (int k = 0; k < K; k += 4) {
            float2 bv[4];
#pragma unroll
            for (int j = 0; j < 4; j++)
                bv[j] = *(const float2*)&Ws[(k + j) * N + tx * 2];
#pragma unroll
            for (int r = 0; r < 8; r++) {
                float4 av = *(const float4*)&Xs[(ty * 8 + r) * K + k];
                acc[r].x += av.x * bv[0].x + av.y * bv[1].x + av.z * bv[2].x + av.w * bv[3].x;
                acc[r].y += av.x * bv[0].y + av.y * bv[1].y + av.z * bv[2].y + av.w * bv[3].y;
            }
        }
#pragma unroll
        for (int r = 0; r < 8; r++) {
            int gr = row0 + ty * 8 + r;
            if (gr < M) {
                float s = scale[gr];
                float2 o = acc[r];
                o.x *= s; o.y *= s;
                *(float2*)&Y[(size_t)gr * N + tx * 2] = o;
            }
        }
    }
}

// ---------------------------------------------------------------------------
// Segment aggregation, C=128: warp per node, lane owns one float4 column group.
// out[n] = (sum_{e in in(n)} h[src_e]) * dinv[n] + bias   (h prescaled by dinv[src])
__global__ void agg128_kernel(const int* __restrict__ rowptr, const int* __restrict__ csr_src,
                              const float* __restrict__ h, const float* __restrict__ dinv,
                              const float* __restrict__ bias, float* __restrict__ out, int N) {
    int warp = (blockIdx.x * blockDim.x + threadIdx.x) >> 5;
    int lane = threadIdx.x & 31;
    if (warp >= N) return;
    int j = rowptr[warp], end = rowptr[warp + 1];
    const float4* hv = (const float4*)h;
    float4 acc = make_float4(0.f, 0.f, 0.f, 0.f);
    for (; j + 4 <= end; j += 4) {
        int s0 = csr_src[j], s1 = csr_src[j + 1], s2 = csr_src[j + 2], s3 = csr_src[j + 3];
        float4 a = hv[(size_t)s0 * 32 + lane];
        float4 b = hv[(size_t)s1 * 32 + lane];
        float4 c = hv[(size_t)s2 * 32 + lane];
        float4 d = hv[(size_t)s3 * 32 + lane];
        acc.x += (a.x + b.x) + (c.x + d.x);
        acc.y += (a.y + b.y) + (c.y + d.y);
        acc.z += (a.z + b.z) + (c.z + d.z);
        acc.w += (a.w + b.w) + (c.w + d.w);
    }
    for (; j < end; j++) {
        int s = csr_src[j];
        float4 a = hv[(size_t)s * 32 + lane];
        acc.x += a.x; acc.y += a.y; acc.z += a.z; acc.w += a.w;
    }
    float dn = dinv[warp];
    float4 bv = ((const float4*)bias)[lane];
    float4 o = make_float4(acc.x * dn + bv.x, acc.y * dn + bv.y,
                           acc.z * dn + bv.z, acc.w * dn + bv.w);
    ((float4*)out)[(size_t)warp * 32 + lane] = o;
}

// Segment aggregation, C=64: warp per node, lane owns one float2 column group.
__global__ void agg64_kernel(const int* __restrict__ rowptr, const int* __restrict__ csr_src,
                             const float* __restrict__ h, const float* __restrict__ dinv,
                             const float* __restrict__ bias, float* __restrict__ out, int N) {
    int warp = (blockIdx.x * blockDim.x + threadIdx.x) >> 5;
    int lane = threadIdx.x & 31;
    if (warp >= N) return;
    int j = rowptr[warp], end = rowptr[warp + 1];
    const float2* hv = (const float2*)h;
    float2 acc = make_float2(0.f, 0.f);
    for (; j + 4 <= end; j += 4) {
        int s0 = csr_src[j], s1 = csr_src[j + 1], s2 = csr_src[j + 2], s3 = csr_src[j + 3];
        float2 a = hv[(size_t)s0 * 32 + lane];
        float2 b = hv[(size_t)s1 * 32 + lane];
        float2 c = hv[(size_t)s2 * 32 + lane];
        float2 d = hv[(size_t)s3 * 32 + lane];
        acc.x += (a.x + b.x) + (c.x + d.x);
        acc.y += (a.y + b.y) + (c.y + d.y);
    }
    for (; j < end; j++) {
        int s = csr_src[j];
        float2 a = hv[(size_t)s * 32 + lane];
        acc.x += a.x; acc.y += a.y;
    }
    float dn = dinv[warp];
    float2 bv = ((const float2*)bias)[lane];
    float2 o = make_float2(acc.x * dn + bv.x, acc.y * dn + bv.y);
    ((float2*)out)[(size_t)warp * 32 + lane] = o;
}

// ---------------------------------------------------------------------------
extern "C" void kernel_launch(void* const* d_in, const int* in_sizes, int n_in,
                              void* d_out, int out_size) {
    const float* x  = (const float*)d_in[0];
    const int*   ei = (const int*)d_in[1];
    const float* W1 = (const float*)d_in[2];
    const float* b1 = (const float*)d_in[3];
    const float* W2 = (const float*)d_in[4];
    const float* b2 = (const float*)d_in[5];
    float* out = (float*)d_out;

    const int N = in_sizes[0] / IN_DIM;
    const int E = in_sizes[1] / 2;
    const int* src = ei;
    const int* dst = ei + E;

    int *p_degi, *p_rowptr, *p_cursor, *p_csr;
    float *p_dinv, *p_h1, *p_acc1, *p_h2;
    cudaGetSymbolAddress((void**)&p_degi,   g_degi);
    cudaGetSymbolAddress((void**)&p_rowptr, g_rowptr);
    cudaGetSymbolAddress((void**)&p_cursor, g_cursor);
    cudaGetSymbolAddress((void**)&p_csr,    g_csr_src);
    cudaGetSymbolAddress((void**)&p_dinv,   g_dinv);
    cudaGetSymbolAddress((void**)&p_h1,     g_h1);
    cudaGetSymbolAddress((void**)&p_acc1,   g_acc1);
    cudaGetSymbolAddress((void**)&p_h2,     g_h2);

    const int smem1 = (IN_DIM * HID_DIM + 64 * IN_DIM) * 4;   // 96 KB
    const int smem2 = (HID_DIM * OUT_DIM + 64 * HID_DIM) * 4; // 64 KB
    cudaFuncSetAttribute((const void*)gemm_kernel<IN_DIM, HID_DIM, false>,
                         cudaFuncAttributeMaxDynamicSharedMemorySize, smem1);
    cudaFuncSetAttribute((const void*)gemm_kernel<HID_DIM, OUT_DIM, true>,
                         cudaFuncAttributeMaxDynamicSharedMemorySize, smem2);

    // --- CSR build (shared by both layers) ---
    cudaMemsetAsync(p_degi, 0, (size_t)N * sizeof(int));
    deg_kernel<<<(E + 255) / 256, 256>>>(dst, p_degi, E);
    scan_kernel<<<1, 1024>>>(p_degi, p_rowptr, p_cursor, p_dinv, N, E);
    fill_kernel<<<(E + 255) / 256, 256>>>(src, dst, p_cursor, p_csr, E);

    // --- layer 1: h1 = dinv .* (x @ W1); acc1 = agg(h1)*dinv + b1 ---
    gemm_kernel<IN_DIM, HID_DIM, false>
        <<<(N + 63) / 64, 256, smem1>>>(x, W1, p_dinv, p_h1, N);
    agg128_kernel<<<(N * 32 + 255) / 256, 256>>>(p_rowptr, p_csr, p_h1, p_dinv, b1, p_acc1, N);

    // --- layer 2: h2 = dinv .* (relu(acc1) @ W2); out = agg(h2)*dinv + b2 ---
    gemm_kernel<HID_DIM, OUT_DIM, true>
        <<<(N + 63) / 64, 256, smem2>>>(p_acc1, W2, p_dinv, p_h2, N);
    agg64_kernel<<<(N * 32 + 255) / 256, 256>>>(p_rowptr, p_csr, p_h2, p_dinv, b2, out, N);
}

// round 5
// speedup vs baseline: 1.0940x; 1.0940x over previous
#include <cuda_runtime.h>
#include <cstdint>

// N_NODES=50000, N_EDGES=800000, IN=128, HID=128, OUT=64. int32 edge indices.
#define NMAX 50048
#define EMAX 800000
#define IN_DIM 128
#define HID_DIM 128
#define OUT_DIM 64

__device__ int   g_degi[NMAX];
__device__ int   g_rowptr[NMAX + 1];
__device__ int   g_cursor[NMAX];
__device__ int   g_csr_src[EMAX];
__device__ float g_dinv[NMAX];
__device__ float g_h1[NMAX * HID_DIM];
__device__ float g_acc1[NMAX * HID_DIM];
__device__ float g_h2[NMAX * OUT_DIM];

typedef unsigned long long ull;

__device__ __forceinline__ ull pack2(float x, float y) {
    ull r;
    asm("mov.b64 %0, {%1, %2};" : "=l"(r) : "f"(x), "f"(y));
    return r;
}
__device__ __forceinline__ void unpack2(ull v, float& x, float& y) {
    asm("mov.b64 {%0, %1}, %2;" : "=f"(x), "=f"(y) : "l"(v));
}
__device__ __forceinline__ void fma2(ull& d, ull a, ull b) {
    asm("fma.rn.f32x2 %0, %1, %2, %0;" : "+l"(d) : "l"(a), "l"(b));
}

// ---------------------------------------------------------------------------
__global__ void deg_kernel(const int* __restrict__ dst, int* __restrict__ degi, int E) {
    int i = blockIdx.x * blockDim.x + threadIdx.x;
    if (i < E) atomicAdd(&degi[dst[i]], 1);
}

__global__ void scan_kernel(const int* __restrict__ degi, int* __restrict__ rowptr,
                            int* __restrict__ cursor, float* __restrict__ dinv,
                            int N, int E) {
    __shared__ int warp_sums[32];
    int t = threadIdx.x;                    // 1024 threads
    int CH = (N + 1023) >> 10;
    int lo = t * CH, hi = min(lo + CH, N);
    int sum = 0;
    for (int i = lo; i < hi; i++) sum += degi[i];

    int lane = t & 31, wid = t >> 5;
    int v = sum;
#pragma unroll
    for (int o = 1; o < 32; o <<= 1) {
        int u = __shfl_up_sync(~0u, v, o);
        if (lane >= o) v += u;
    }
    if (lane == 31) warp_sums[wid] = v;
    __syncthreads();
    if (wid == 0) {
        int w = warp_sums[lane];
#pragma unroll
        for (int o = 1; o < 32; o <<= 1) {
            int u = __shfl_up_sync(~0u, w, o);
            if (lane >= o) w += u;
        }
        warp_sums[lane] = w;
    }
    __syncthreads();
    int run = v - sum + (wid > 0 ? warp_sums[wid - 1] : 0);
    for (int i = lo; i < hi; i++) {
        int d = degi[i];
        rowptr[i] = run;
        cursor[i] = run;
        dinv[i] = d > 0 ? rsqrtf((float)d) : 0.0f;
        run += d;
    }
    if (t == 0) rowptr[N] = E;
}

__global__ void fill_kernel(const int* __restrict__ src, const int* __restrict__ dst,
                            int* __restrict__ cursor, int* __restrict__ csr_src, int E) {
    int e = blockIdx.x * blockDim.x + threadIdx.x;
    if (e < E) {
        int pos = atomicAdd(&cursor[dst[e]], 1);
        csr_src[pos] = src[e];
    }
}

// ---------------------------------------------------------------------------
// Tiled fp32 GEMM with packed f32x2 FMA: Y = act(X) @ W, then Y[row] *= scale[row].
// 256 threads, 64-row tile, W resident in smem, conflict-free vector LDS.
template <int K, int N, bool RELU>
__global__ void gemm_kernel(const float* __restrict__ X, const float* __restrict__ W,
                            const float* __restrict__ scale,
                            float* __restrict__ Y, int M) {
    constexpr int ROWS = 64;
    constexpr int CPT = N / 32;
    extern __shared__ float smem[];
    float* Ws = smem;              // K*N
    float* Xs = smem + K * N;      // ROWS*K

    int t = threadIdx.x;
    for (int i = t; i < K * N / 4; i += 256)
        ((float4*)Ws)[i] = ((const float4*)W)[i];

    int row0 = blockIdx.x * ROWS;
    constexpr int K4 = K / 4;
    for (int i = t; i < ROWS * K4; i += 256) {
        int gr = row0 + i / K4;
        float4 v = make_float4(0.f, 0.f, 0.f, 0.f);
        if (gr < M) v = ((const float4*)X)[(size_t)gr * K4 + (i % K4)];
        if (RELU) {
            v.x = fmaxf(v.x, 0.f); v.y = fmaxf(v.y, 0.f);
            v.z = fmaxf(v.z, 0.f); v.w = fmaxf(v.w, 0.f);
        }
        ((float4*)Xs)[i] = v;
    }
    __syncthreads();

    int tx = t & 31;
    int ty = t >> 5;

    if constexpr (CPT == 4) {
        ull accxy[8], acczw[8];
#pragma unroll
        for (int r = 0; r < 8; r++) { accxy[r] = 0ull; acczw[r] = 0ull; }
#pragma unroll 2
        for (int k = 0; k < K; k += 4) {
            ull bxy[4], bzw[4];
#pragma unroll
            for (int j = 0; j < 4; j++) {
                longlong2 bb = *(const longlong2*)&Ws[(k + j) * N + tx * 4];
                bxy[j] = (ull)bb.x; bzw[j] = (ull)bb.y;
            }
#pragma unroll
            for (int r = 0; r < 8; r++) {
                float4 av = *(const float4*)&Xs[(ty * 8 + r) * K + k];
                ull a0 = pack2(av.x, av.x), a1 = pack2(av.y, av.y);
                ull a2 = pack2(av.z, av.z), a3 = pack2(av.w, av.w);
                fma2(accxy[r], a0, bxy[0]); fma2(acczw[r], a0, bzw[0]);
                fma2(accxy[r], a1, bxy[1]); fma2(acczw[r], a1, bzw[1]);
                fma2(accxy[r], a2, bxy[2]); fma2(acczw[r], a2, bzw[2]);
                fma2(accxy[r], a3, bxy[3]); fma2(acczw[r], a3, bzw[3]);
            }
        }
#pragma unroll
        for (int r = 0; r < 8; r++) {
            int gr = row0 + ty * 8 + r;
            if (gr < M) {
                float s = scale[gr];
                float4 o;
                unpack2(accxy[r], o.x, o.y);
                unpack2(acczw[r], o.z, o.w);
                o.x *= s; o.y *= s; o.z *= s; o.w *= s;
                *(float4*)&Y[(size_t)gr * N + tx * 4] = o;
            }
        }
    } else {
        ull acc[8];
#pragma unroll
        for (int r = 0; r < 8; r++) acc[r] = 0ull;
#pragma unroll 2
        for (int k = 0; k < K; k += 4) {
            ull bk[4];
#pragma unroll
            for (int j = 0; j < 4; j++)
                bk[j] = *(const ull*)&Ws[(k + j) * N + tx * 2];
#pragma unroll
            for (int r = 0; r < 8; r++) {
                float4 av = *(const float4*)&Xs[(ty * 8 + r) * K + k];
                fma2(acc[r], pack2(av.x, av.x), bk[0]);
                fma2(acc[r], pack2(av.y, av.y), bk[1]);
                fma2(acc[r], pack2(av.z, av.z), bk[2]);
                fma2(acc[r], pack2(av.w, av.w), bk[3]);
            }
        }
#pragma unroll
        for (int r = 0; r < 8; r++) {
            int gr = row0 + ty * 8 + r;
            if (gr < M) {
                float s = scale[gr];
                float2 o;
                unpack2(acc[r], o.x, o.y);
                o.x *= s; o.y *= s;
                *(float2*)&Y[(size_t)gr * N + tx * 2] = o;
            }
        }
    }
}

// ---------------------------------------------------------------------------
// Segment aggregation, C=128: warp per node, lane owns one float4, MLP-8 unroll.
__global__ void agg128_kernel(const int* __restrict__ rowptr, const int* __restrict__ csr_src,
                              const float* __restrict__ h, const float* __restrict__ dinv,
                              const float* __restrict__ bias, float* __restrict__ out, int N) {
    int warp = (blockIdx.x * blockDim.x + threadIdx.x) >> 5;
    int lane = threadIdx.x & 31;
    if (warp >= N) return;
    int j = rowptr[warp], end = rowptr[warp + 1];
    const float4* hv = (const float4*)h;
    float4 acc = make_float4(0.f, 0.f, 0.f, 0.f);
    for (; j + 8 <= end; j += 8) {
        int s[8];
#pragma unroll
        for (int u = 0; u < 8; u++) s[u] = csr_src[j + u];
        float4 v[8];
#pragma unroll
        for (int u = 0; u < 8; u++) v[u] = hv[(size_t)s[u] * 32 + lane];
#pragma unroll
        for (int u = 0; u < 8; u++) {
            acc.x += v[u].x; acc.y += v[u].y; acc.z += v[u].z; acc.w += v[u].w;
        }
    }
    for (; j < end; j++) {
        int s = csr_src[j];
        float4 a = hv[(size_t)s * 32 + lane];
        acc.x += a.x; acc.y += a.y; acc.z += a.z; acc.w += a.w;
    }
    float dn = dinv[warp];
    float4 bv = ((const float4*)bias)[lane];
    float4 o = make_float4(acc.x * dn + bv.x, acc.y * dn + bv.y,
                           acc.z * dn + bv.z, acc.w * dn + bv.w);
    ((float4*)out)[(size_t)warp * 32 + lane] = o;
}

// Segment aggregation, C=64: warp per node, lane owns one float2, MLP-8 unroll.
__global__ void agg64_kernel(const int* __restrict__ rowptr, const int* __restrict__ csr_src,
                             const float* __restrict__ h, const float* __restrict__ dinv,
                             const float* __restrict__ bias, float* __restrict__ out, int N) {
    int warp = (blockIdx.x * blockDim.x + threadIdx.x) >> 5;
    int lane = threadIdx.x & 31;
    if (warp >= N) return;
    int j = rowptr[warp], end = rowptr[warp + 1];
    const float2* hv = (const float2*)h;
    float2 acc = make_float2(0.f, 0.f);
    for (; j + 8 <= end; j += 8) {
        int s[8];
#pragma unroll
        for (int u = 0; u < 8; u++) s[u] = csr_src[j + u];
        float2 v[8];
#pragma unroll
        for (int u = 0; u < 8; u++) v[u] = hv[(size_t)s[u] * 32 + lane];
#pragma unroll
        for (int u = 0; u < 8; u++) { acc.x += v[u].x; acc.y += v[u].y; }
    }
    for (; j < end; j++) {
        int s = csr_src[j];
        float2 a = hv[(size_t)s * 32 + lane];
        acc.x += a.x; acc.y += a.y;
    }
    float dn = dinv[warp];
    float2 bv = ((const float2*)bias)[lane];
    float2 o = make_float2(acc.x * dn + bv.x, acc.y * dn + bv.y);
    ((float2*)out)[(size_t)warp * 32 + lane] = o;
}

// ---------------------------------------------------------------------------
extern "C" void kernel_launch(void* const* d_in, const int* in_sizes, int n_in,
                              void* d_out, int out_size) {
    const float* x  = (const float*)d_in[0];
    const int*   ei = (const int*)d_in[1];
    const float* W1 = (const float*)d_in[2];
    const float* b1 = (const float*)d_in[3];
    const float* W2 = (const float*)d_in[4];
    const float* b2 = (const float*)d_in[5];
    float* out = (float*)d_out;

    const int N = in_sizes[0] / IN_DIM;
    const int E = in_sizes[1] / 2;
    const int* src = ei;
    const int* dst = ei + E;

    int *p_degi, *p_rowptr, *p_cursor, *p_csr;
    float *p_dinv, *p_h1, *p_acc1, *p_h2;
    cudaGetSymbolAddress((void**)&p_degi,   g_degi);
    cudaGetSymbolAddress((void**)&p_rowptr, g_rowptr);
    cudaGetSymbolAddress((void**)&p_cursor, g_cursor);
    cudaGetSymbolAddress((void**)&p_csr,    g_csr_src);
    cudaGetSymbolAddress((void**)&p_dinv,   g_dinv);
    cudaGetSymbolAddress((void**)&p_h1,     g_h1);
    cudaGetSymbolAddress((void**)&p_acc1,   g_acc1);
    cudaGetSymbolAddress((void**)&p_h2,     g_h2);

    const int smem1 = (IN_DIM * HID_DIM + 64 * IN_DIM) * 4;   // 96 KB
    const int smem2 = (HID_DIM * OUT_DIM + 64 * HID_DIM) * 4; // 64 KB
    cudaFuncSetAttribute((const void*)gemm_kernel<IN_DIM, HID_DIM, false>,
                         cudaFuncAttributeMaxDynamicSharedMemorySize, smem1);
    cudaFuncSetAttribute((const void*)gemm_kernel<HID_DIM, OUT_DIM, true>,
                         cudaFuncAttributeMaxDynamicSharedMemorySize, smem2);

    // --- CSR build (shared by both layers) ---
    cudaMemsetAsync(p_degi, 0, (size_t)N * sizeof(int));
    deg_kernel<<<(E + 255) / 256, 256>>>(dst, p_degi, E);
    scan_kernel<<<1, 1024>>>(p_degi, p_rowptr, p_cursor, p_dinv, N, E);
    fill_kernel<<<(E + 255) / 256, 256>>>(src, dst, p_cursor, p_csr, E);

    // --- layer 1 ---
    gemm_kernel<IN_DIM, HID_DIM, false>
        <<<(N + 63) / 64, 256, smem1>>>(x, W1, p_dinv, p_h1, N);
    agg128_kernel<<<(N * 32 + 255) / 256, 256>>>(p_rowptr, p_csr, p_h1, p_dinv, b1, p_acc1, N);

    // --- layer 2 ---
    gemm_kernel<HID_DIM, OUT_DIM, true>
        <<<(N + 63) / 64, 256, smem2>>>(p_acc1, W2, p_dinv, p_h2, N);
    agg64_kernel<<<(N * 32 + 255) / 256, 256>>>(p_rowptr, p_csr, p_h2, p_dinv, b2, out, N);
}